// round 5
// baseline (speedup 1.0000x reference)
#include <cuda_runtime.h>
#include <cuda_bf16.h>
#include <cstdint>

// Problem constants
#define BB 2
#define SS 2048
#define DD 1024
#define HH 16
#define HKK 4
#define HDD 64
#define WINN 1024
#define EE 8
#define DHH 2048
#define ROWS (BB*SS)          // 4096
#define NASSIGN (ROWS*2)      // 8192

// GEMM tile config (128x128, modes 0/3)
#define BM 128
#define BN 128
#define BK 16
#define STAGES 4
#define SA 20
#define SBW 136
#define ASZ (BM*SA)
#define BSZ (BK*SBW)
#define STAGE_F (ASZ+BSZ)
#define GEMM_SMEM (STAGES*STAGE_F*4)

// MoE GEMM tile config (256x128, warp tile 64x64)
#define BM2 256
#define SA2 20
#define ASZ2 (BM2*SA2)         // 5120
#define STAGE2_F (ASZ2+BSZ)    // 7296
#define MOE_SMEM (STAGES*STAGE2_F*4)   // 116736

// ---------------- scratch ----------------
__device__ __align__(16) float g_hn[ROWS*DD];
__device__ __align__(16) float g_q [ROWS*HH*HDD];
__device__ __align__(16) float g_k [ROWS*HKK*HDD];
__device__ __align__(16) float g_v [ROWS*HKK*HDD];
__device__ __align__(16) float g_o [ROWS*HH*HDD];
__device__ __align__(16) float g_h [ROWS*DD];
__device__ __align__(16) float g_fn[ROWS*DD];
__device__ __align__(16) float g_h1[NASSIGN*DHH];
__device__ __align__(16) float g_r [NASSIGN*DD];
__device__ int   g_counts[EE];
__device__ int   g_cursor[EE];
__device__ int   g_offsets[EE+1];
__device__ int   g_topi[NASSIGN];
__device__ float g_topg[NASSIGN];
__device__ int   g_arow[NASSIGN];
__device__ float g_agate[NASSIGN];
__device__ int   g_adst[NASSIGN];

// ---------------- helpers ----------------
__device__ __forceinline__ uint32_t f2tf(float f) {
    uint32_t r; asm("cvt.rna.tf32.f32 %0, %1;" : "=r"(r) : "f"(f)); return r;
}

__device__ __forceinline__ void mma_tf32(float* c, const uint32_t* a, uint32_t b0, uint32_t b1) {
    asm volatile("mma.sync.aligned.m16n8k8.row.col.f32.tf32.tf32.f32 "
        "{%0,%1,%2,%3}, {%4,%5,%6,%7}, {%8,%9}, {%0,%1,%2,%3};"
        : "+f"(c[0]), "+f"(c[1]), "+f"(c[2]), "+f"(c[3])
        : "r"(a[0]), "r"(a[1]), "r"(a[2]), "r"(a[3]), "r"(b0), "r"(b1));
}

__device__ __forceinline__ void cp16(float* smem_dst, const float* gsrc) {
    uint32_t s = (uint32_t)__cvta_generic_to_shared(smem_dst);
    asm volatile("cp.async.cg.shared.global [%0], [%1], 16;\n" :: "r"(s), "l"(gsrc));
}
__device__ __forceinline__ void cp_commit() { asm volatile("cp.async.commit_group;\n"); }
template<int N> __device__ __forceinline__ void cp_wait() {
    asm volatile("cp.async.wait_group %0;\n" :: "n"(N));
}

// ---------------- small kernels ----------------
__global__ void zero_kernel() {
    int t = threadIdx.x;
    if (t < EE) { g_counts[t] = 0; g_cursor[t] = 0; }
}

__global__ void rmsnorm_kernel(const float* __restrict__ x, const float* __restrict__ w,
                               float* __restrict__ y, float eps) {
    int row = blockIdx.x;
    int tid = threadIdx.x;
    const float* xr = x + (size_t)row * DD;
    float4 v = *(const float4*)(xr + tid * 4);
    float s = v.x*v.x + v.y*v.y + v.z*v.z + v.w*v.w;
    __shared__ float red[256];
    red[tid] = s; __syncthreads();
    for (int st = 128; st > 0; st >>= 1) {
        if (tid < st) red[tid] += red[tid + st];
        __syncthreads();
    }
    float rms = rsqrtf(red[0] / (float)DD + eps);
    float4 wv = *(const float4*)(w + tid * 4);
    float4 ov;
    ov.x = v.x * rms * wv.x; ov.y = v.y * rms * wv.y;
    ov.z = v.z * rms * wv.z; ov.w = v.w * rms * wv.w;
    *(float4*)(y + (size_t)row * DD + tid * 4) = ov;
}

// ---------------- tf32 GEMM 128x128, cp.async pipeline (modes 0/3) ----------------
// MODE 0: C = A@B (+X). ROPE optionally.
// MODE 3: fused K/V proj: grid (4, 32); blockIdx.x>>1: 0->wk->g_k (ROPE), 1->wv->g_v.
template<int MODE, bool ROPE>
__global__ __launch_bounds__(256, 2)
void tcgemm(const float* __restrict__ Ag, const float* __restrict__ Bg,
            const float* __restrict__ Xg, float* __restrict__ Cg,
            int M, int N, int K,
            const float* __restrict__ fcos, const float* __restrict__ fsin)
{
    extern __shared__ __align__(16) float sm[];
    const int tid  = threadIdx.x;
    const int rt0  = blockIdx.y * BM;
    int col0 = blockIdx.x * BN;
    const float* Bsel = Bg;
    float* Csel = Cg;
    int sel = 0;

    if (MODE == 3) {
        sel = blockIdx.x >> 1;
        col0 = (blockIdx.x & 1) * BN;
        if (sel) { Bsel = Xg; Csel = g_v; } else { Csel = g_k; }
    }

    const int am0 = tid >> 2;
    const int kc4 = (tid & 3) * 4;
    const int bkr = tid >> 5;
    const int bnc = (tid & 31) * 4;

    const float* arow_ptr[2];
    #pragma unroll
    for (int i = 0; i < 2; i++)
        arow_ptr[i] = Ag + (size_t)(rt0 + am0 + i * 64) * K;
    const float* Brow = Bsel + col0;

    const int nk = K / BK;

    #pragma unroll
    for (int s = 0; s < STAGES - 1; s++) {
        if (s < nk) {
            float* base = sm + s * STAGE_F;
            const int k0 = s * BK;
            cp16(base + am0*SA + kc4,        arow_ptr[0] + k0 + kc4);
            cp16(base + (64+am0)*SA + kc4,   arow_ptr[1] + k0 + kc4);
            float* bb = base + ASZ;
            cp16(bb + bkr*SBW + bnc,         Brow + (size_t)(k0 + bkr) * N + bnc);
            cp16(bb + (8+bkr)*SBW + bnc,     Brow + (size_t)(k0 + 8 + bkr) * N + bnc);
        }
        cp_commit();
    }

    const int lane = tid & 31, warp = tid >> 5;
    const int wm = warp & 3, wn = warp >> 2;
    const int g = lane >> 2, cq = lane & 3;

    float acc[2][8][4];
    #pragma unroll
    for (int mi = 0; mi < 2; mi++)
        #pragma unroll
        for (int ni = 0; ni < 8; ni++)
            #pragma unroll
            for (int j = 0; j < 4; j++) acc[mi][ni][j] = 0.f;

    for (int kt = 0; kt < nk; kt++) {
        cp_wait<STAGES-2>();
        __syncthreads();
        {
            const int pf = kt + STAGES - 1;
            if (pf < nk) {
                float* base = sm + (pf % STAGES) * STAGE_F;
                const int k0 = pf * BK;
                cp16(base + am0*SA + kc4,        arow_ptr[0] + k0 + kc4);
                cp16(base + (64+am0)*SA + kc4,   arow_ptr[1] + k0 + kc4);
                float* bb = base + ASZ;
                cp16(bb + bkr*SBW + bnc,         Brow + (size_t)(k0 + bkr) * N + bnc);
                cp16(bb + (8+bkr)*SBW + bnc,     Brow + (size_t)(k0 + 8 + bkr) * N + bnc);
            }
            cp_commit();
        }
        const uint32_t* Au = (const uint32_t*)(sm + (kt % STAGES) * STAGE_F);
        const uint32_t* Bu = Au + ASZ;
        #pragma unroll
        for (int ks = 0; ks < 2; ks++) {
            const int kb = ks * 8 + cq;
            uint32_t a[2][4];
            #pragma unroll
            for (int mi = 0; mi < 2; mi++) {
                const int m = wm*32 + mi*16 + g;
                a[mi][0] = Au[m*SA + kb];
                a[mi][1] = Au[(m+8)*SA + kb];
                a[mi][2] = Au[m*SA + kb + 4];
                a[mi][3] = Au[(m+8)*SA + kb + 4];
            }
            #pragma unroll
            for (int ni = 0; ni < 8; ni++) {
                const int n = wn*64 + ni*8 + g;
                uint32_t b0 = Bu[kb*SBW + n];
                uint32_t b1 = Bu[(kb+4)*SBW + n];
                mma_tf32(acc[0][ni], a[0], b0, b1);
                mma_tf32(acc[1][ni], a[1], b0, b1);
            }
        }
    }

    #pragma unroll
    for (int mi = 0; mi < 2; mi++) {
        #pragma unroll
        for (int rs = 0; rs < 2; rs++) {
            const int rr = wm*32 + mi*16 + g + rs*8;
            const int grow = rt0 + rr;
            #pragma unroll
            for (int ni = 0; ni < 8; ni++) {
                const int cc = wn*64 + ni*8 + 2*cq;
                float v0 = acc[mi][ni][rs*2+0];
                float v1 = acc[mi][ni][rs*2+1];
                const int NN = (MODE == 3) ? 256 : N;
                size_t base = (size_t)grow * NN + col0 + cc;
                if (ROPE && (MODE == 0 || sel == 0)) {
                    const int s = grow & (SS - 1);
                    const int i = ((col0 + cc) & 63) >> 1;
                    float cth = fcos[s*32 + i], sth = fsin[s*32 + i];
                    float o0 = v0 * cth - v1 * sth;
                    float o1 = v0 * sth + v1 * cth;
                    v0 = o0; v1 = o1;
                }
                if (MODE == 0 && Xg) { v0 += Xg[base]; v1 += Xg[base+1]; }
                float2 ov; ov.x = v0; ov.y = v1;
                *(float2*)&Csel[base] = ov;
            }
        }
    }
}

// ---------------- tf32 MoE GEMM 256x128, warp tile 64x64 ----------------
// MODE 1: silu(fn_gathered @ w1[e]) -> g_h1     grid (DHH/128, 32, 8)
// MODE 2: gate * (g_h1 @ w2[e]) scatter -> g_r  grid (DD/128, 32, 8)
template<int MODE>
__global__ __launch_bounds__(256, 1)
void tcgemm_moe(const float* __restrict__ Ag, const float* __restrict__ Bg,
                int N, int K)
{
    extern __shared__ __align__(16) float sm[];
    __shared__ int   rows_s[BM2];
    __shared__ int   adst_s[BM2];
    __shared__ float agate_s[BM2];

    const int tid  = threadIdx.x;
    const int rt0  = blockIdx.y * BM2;
    const int col0 = blockIdx.x * BN;
    const int e = blockIdx.z;
    const int cnt = g_counts[e];
    if (rt0 >= cnt) return;
    const int off = g_offsets[e];
    const float* Bsel = Bg + (size_t)e * (size_t)K * N;

    if (MODE == 1) {
        int r = rt0 + tid; if (r >= cnt) r = cnt - 1;
        rows_s[tid] = g_arow[off + r];
    } else {
        int r = rt0 + tid; if (r >= cnt) r = cnt - 1;
        adst_s[tid]  = g_adst[off + r];
        agate_s[tid] = g_agate[off + r];
    }
    __syncthreads();

    const int am0 = tid >> 2;                  // A rows am0 + 64*i
    const int kc4 = (tid & 3) * 4;
    const int bkr = tid >> 5;
    const int bnc = (tid & 31) * 4;

    const float* arow_ptr[4];
    #pragma unroll
    for (int i = 0; i < 4; i++) {
        int r = am0 + i * 64;
        size_t grow;
        if (MODE == 1) grow = (size_t)rows_s[r];
        else { int rr = rt0 + r; if (rr >= cnt) rr = cnt - 1; grow = (size_t)(off + rr); }
        arow_ptr[i] = (MODE == 2 ? (const float*)g_h1 : Ag) + grow * (size_t)K;
    }
    const float* Brow = Bsel + col0;

    const int nk = K / BK;

    #pragma unroll
    for (int s = 0; s < STAGES - 1; s++) {
        float* base = sm + s * STAGE2_F;
        const int k0 = s * BK;
        #pragma unroll
        for (int i = 0; i < 4; i++)
            cp16(base + (am0 + 64*i)*SA2 + kc4, arow_ptr[i] + k0 + kc4);
        float* bb = base + ASZ2;
        cp16(bb + bkr*SBW + bnc,      Brow + (size_t)(k0 + bkr) * N + bnc);
        cp16(bb + (8+bkr)*SBW + bnc,  Brow + (size_t)(k0 + 8 + bkr) * N + bnc);
        cp_commit();
    }

    const int lane = tid & 31, warp = tid >> 5;
    const int wm = warp & 3, wn = warp >> 2;       // 4x2
    const int g = lane >> 2, cq = lane & 3;

    float acc[4][8][4];
    #pragma unroll
    for (int mi = 0; mi < 4; mi++)
        #pragma unroll
        for (int ni = 0; ni < 8; ni++)
            #pragma unroll
            for (int j = 0; j < 4; j++) acc[mi][ni][j] = 0.f;

    for (int kt = 0; kt < nk; kt++) {
        cp_wait<STAGES-2>();
        __syncthreads();
        {
            const int pf = kt + STAGES - 1;
            if (pf < nk) {
                float* base = sm + (pf % STAGES) * STAGE2_F;
                const int k0 = pf * BK;
                #pragma unroll
                for (int i = 0; i < 4; i++)
                    cp16(base + (am0 + 64*i)*SA2 + kc4, arow_ptr[i] + k0 + kc4);
                float* bb = base + ASZ2;
                cp16(bb + bkr*SBW + bnc,      Brow + (size_t)(k0 + bkr) * N + bnc);
                cp16(bb + (8+bkr)*SBW + bnc,  Brow + (size_t)(k0 + 8 + bkr) * N + bnc);
            }
            cp_commit();
        }
        const uint32_t* Au = (const uint32_t*)(sm + (kt % STAGES) * STAGE2_F);
        const uint32_t* Bu = Au + ASZ2;
        #pragma unroll
        for (int ks = 0; ks < 2; ks++) {
            const int kb = ks * 8 + cq;
            uint32_t a[4][4];
            #pragma unroll
            for (int mi = 0; mi < 4; mi++) {
                const int m = wm*64 + mi*16 + g;
                a[mi][0] = Au[m*SA2 + kb];
                a[mi][1] = Au[(m+8)*SA2 + kb];
                a[mi][2] = Au[m*SA2 + kb + 4];
                a[mi][3] = Au[(m+8)*SA2 + kb + 4];
            }
            uint32_t b[8][2];
            #pragma unroll
            for (int ni = 0; ni < 8; ni++) {
                const int n = wn*64 + ni*8 + g;
                b[ni][0] = Bu[kb*SBW + n];
                b[ni][1] = Bu[(kb+4)*SBW + n];
            }
            #pragma unroll
            for (int mi = 0; mi < 4; mi++)
                #pragma unroll
                for (int ni = 0; ni < 8; ni++)
                    mma_tf32(acc[mi][ni], a[mi], b[ni][0], b[ni][1]);
        }
    }

    #pragma unroll
    for (int mi = 0; mi < 4; mi++) {
        #pragma unroll
        for (int rs = 0; rs < 2; rs++) {
            const int rr = wm*64 + mi*16 + g + rs*8;
            const int r = rt0 + rr;
            if (r < cnt) {
                if (MODE == 1) {
                    #pragma unroll
                    for (int ni = 0; ni < 8; ni++) {
                        const int cc = wn*64 + ni*8 + 2*cq;
                        float v0 = acc[mi][ni][rs*2+0];
                        float v1 = acc[mi][ni][rs*2+1];
                        size_t base = (size_t)(off + r) * DHH + col0 + cc;
                        float2 ov;
                        ov.x = v0 / (1.f + __expf(-v0));
                        ov.y = v1 / (1.f + __expf(-v1));
                        *(float2*)&g_h1[base] = ov;
                    }
                } else {
                    const int dst = adst_s[rr];
                    const float gate = agate_s[rr];
                    #pragma unroll
                    for (int ni = 0; ni < 8; ni++) {
                        const int cc = wn*64 + ni*8 + 2*cq;
                        size_t base = (size_t)dst * DD + col0 + cc;
                        float2 ov;
                        ov.x = gate * acc[mi][ni][rs*2+0];
                        ov.y = gate * acc[mi][ni][rs*2+1];
                        *(float2*)&g_r[base] = ov;
                    }
                }
            }
        }
    }
}

// ---------------- tensor-core flash attention ----------------
#define KPAD 68
extern __shared__ uint32_t sm_attn[];
__global__ __launch_bounds__(256)
void attn_tc(const float* __restrict__ q, const float* __restrict__ k,
             const float* __restrict__ v) {
    uint32_t* Ks = sm_attn;
    uint32_t* Vs = sm_attn + 64*KPAD;
    uint32_t* Ps = sm_attn + 2*64*KPAD;
    const int qt = blockIdx.x, h = blockIdx.y, b = blockIdx.z, hk = h >> 2;
    const int q0 = qt * 128;
    const int tid = threadIdx.x, lane = tid & 31, w = tid >> 5;
    const int g = lane >> 2, cq = lane & 3;

    {
        int row = tid >> 1, dh = (tid & 1) * 32;
        const float* src = q + ((size_t)(b * SS + q0 + row)) * (HH*HDD) + h * HDD + dh;
        #pragma unroll
        for (int i = 0; i < 8; i++) {
            float4 f = *(const float4*)(src + 4*i);
            uint32_t* dst = &Ps[row*KPAD + dh + 4*i];
            dst[0]=f2tf(f.x); dst[1]=f2tf(f.y); dst[2]=f2tf(f.z); dst[3]=f2tf(f.w);
        }
    }
    __syncthreads();
    uint32_t Qa[8][4];
    {
        const int r0 = w*16 + g;
        #pragma unroll
        for (int s = 0; s < 8; s++) {
            Qa[s][0] = Ps[r0*KPAD + 8*s + cq];
            Qa[s][1] = Ps[(r0+8)*KPAD + 8*s + cq];
            Qa[s][2] = Ps[r0*KPAD + 8*s + cq + 4];
            Qa[s][3] = Ps[(r0+8)*KPAD + 8*s + cq + 4];
        }
    }
    __syncthreads();

    float Oacc[8][4];
    #pragma unroll
    for (int nt = 0; nt < 8; nt++)
        #pragma unroll
        for (int j = 0; j < 4; j++) Oacc[nt][j] = 0.f;
    float m[2] = {-1e30f, -1e30f}, l[2] = {0.f, 0.f};

    int jlo = q0 - (WINN - 1); if (jlo < 0) jlo = 0;
    const int jt0 = jlo >> 6, jt1 = (q0 + 127) >> 6;
    const int qwmin = q0 + w*16, qwmax = qwmin + 15;

    for (int jt = jt0; jt <= jt1; jt++) {
        const int j0 = jt << 6;
        {
            int key = tid >> 2, d0 = (tid & 3) * 16;
            const float* src = k + ((size_t)(b * SS + j0 + key)) * (HKK*HDD) + hk * HDD + d0;
            #pragma unroll
            for (int i = 0; i < 4; i++) {
                float4 f = *(const float4*)(src + 4*i);
                uint4 u = make_uint4(f2tf(f.x), f2tf(f.y), f2tf(f.z), f2tf(f.w));
                *(uint4*)&Ks[key*KPAD + d0 + 4*i] = u;
            }
            int vkey = tid & 63, vd0 = (tid >> 6) * 16;
            const float* vsrc = v + ((size_t)(b * SS + j0 + vkey)) * (HKK*HDD) + hk * HDD + vd0;
            #pragma unroll
            for (int i = 0; i < 4; i++) {
                float4 f = *(const float4*)(vsrc + 4*i);
                Vs[(vd0+4*i+0)*KPAD + vkey] = f2tf(f.x);
                Vs[(vd0+4*i+1)*KPAD + vkey] = f2tf(f.y);
                Vs[(vd0+4*i+2)*KPAD + vkey] = f2tf(f.z);
                Vs[(vd0+4*i+3)*KPAD + vkey] = f2tf(f.w);
            }
        }
        __syncthreads();
        float sacc[8][4];
        #pragma unroll
        for (int nt = 0; nt < 8; nt++)
            #pragma unroll
            for (int j = 0; j < 4; j++) sacc[nt][j] = 0.f;
        #pragma unroll
        for (int s = 0; s < 8; s++) {
            #pragma unroll
            for (int nt = 0; nt < 8; nt++) {
                uint32_t b0 = Ks[(nt*8+g)*KPAD + 8*s + cq];
                uint32_t b1 = Ks[(nt*8+g)*KPAD + 8*s + cq + 4];
                mma_tf32(sacc[nt], Qa[s], b0, b1);
            }
        }
        const bool need_mask = !((j0 + 63 <= qwmin) && (qwmax - j0 < WINN));
        #pragma unroll
        for (int nt = 0; nt < 8; nt++) {
            #pragma unroll
            for (int j = 0; j < 4; j++) {
                float sv = sacc[nt][j] * 0.125f;
                if (need_mask) {
                    int qi = qwmin + g + 8 * (j >> 1);
                    int kj = j0 + nt*8 + 2*cq + (j & 1);
                    if (!(kj <= qi && qi - kj < WINN)) sv = -1e30f;
                }
                sacc[nt][j] = sv;
            }
        }
        #pragma unroll
        for (int rs = 0; rs < 2; rs++) {
            float mx = -1e30f;
            #pragma unroll
            for (int nt = 0; nt < 8; nt++)
                mx = fmaxf(mx, fmaxf(sacc[nt][2*rs], sacc[nt][2*rs+1]));
            mx = fmaxf(mx, __shfl_xor_sync(0xffffffffu, mx, 1));
            mx = fmaxf(mx, __shfl_xor_sync(0xffffffffu, mx, 2));
            float mnew = fmaxf(m[rs], mx);
            float alpha = __expf(m[rs] - mnew);
            float sum = 0.f;
            const int row = w*16 + g + 8*rs;
            #pragma unroll
            for (int nt = 0; nt < 8; nt++) {
                float p0 = sacc[nt][2*rs];
                float p1 = sacc[nt][2*rs+1];
                p0 = (p0 <= -1e29f) ? 0.f : __expf(p0 - mnew);
                p1 = (p1 <= -1e29f) ? 0.f : __expf(p1 - mnew);
                sum += p0 + p1;
                uint2 u; u.x = f2tf(p0); u.y = f2tf(p1);
                *(uint2*)&Ps[row*KPAD + nt*8 + 2*cq] = u;
            }
            sum += __shfl_xor_sync(0xffffffffu, sum, 1);
            sum += __shfl_xor_sync(0xffffffffu, sum, 2);
            l[rs] = l[rs] * alpha + sum;
            m[rs] = mnew;
            #pragma unroll
            for (int nt = 0; nt < 8; nt++) {
                Oacc[nt][2*rs]   *= alpha;
                Oacc[nt][2*rs+1] *= alpha;
            }
        }
        __syncwarp();
        #pragma unroll
        for (int s = 0; s < 8; s++) {
            const int r0 = w*16 + g;
            uint32_t a[4];
            a[0] = Ps[r0*KPAD + 8*s + cq];
            a[1] = Ps[(r0+8)*KPAD + 8*s + cq];
            a[2] = Ps[r0*KPAD + 8*s + cq + 4];
            a[3] = Ps[(r0+8)*KPAD + 8*s + cq + 4];
            #pragma unroll
            for (int nt = 0; nt < 8; nt++) {
                uint32_t b0 = Vs[(nt*8+g)*KPAD + 8*s + cq];
                uint32_t b1 = Vs[(nt*8+g)*KPAD + 8*s + cq + 4];
                mma_tf32(Oacc[nt], a, b0, b1);
            }
        }
        __syncthreads();
    }
    #pragma unroll
    for (int rs = 0; rs < 2; rs++) {
        const float inv = 1.f / l[rs];
        const int row = q0 + w*16 + g + 8*rs;
        #pragma unroll
        for (int nt = 0; nt < 8; nt++) {
            float2 ov;
            ov.x = Oacc[nt][2*rs]   * inv;
            ov.y = Oacc[nt][2*rs+1] * inv;
            *(float2*)&g_o[((size_t)(b * SS + row)) * (HH*HDD) + h * HDD + nt*8 + 2*cq] = ov;
        }
    }
}

// ---------------- router / MoE bookkeeping ----------------
__global__ void router_kernel(const float* __restrict__ fn, const float* __restrict__ rw) {
    const int row = blockIdx.x;
    const int tid = threadIdx.x;           // 128
    float l[EE] = {};
    for (int d = tid; d < DD; d += 128) {
        float x = fn[(size_t)row * DD + d];
        #pragma unroll
        for (int e = 0; e < EE; e++) l[e] += x * rw[d * EE + e];
    }
    __shared__ float part[EE][128];
    #pragma unroll
    for (int e = 0; e < EE; e++) part[e][tid] = l[e];
    __syncthreads();
    for (int st = 64; st > 0; st >>= 1) {
        if (tid < st) {
            #pragma unroll
            for (int e = 0; e < EE; e++) part[e][tid] += part[e][tid + st];
        }
        __syncthreads();
    }
    if (tid == 0) {
        float lg[EE];
        #pragma unroll
        for (int e = 0; e < EE; e++) lg[e] = part[e][0];
        int i1 = 0;
        #pragma unroll
        for (int e = 1; e < EE; e++) if (lg[e] > lg[i1]) i1 = e;
        int i2 = (i1 == 0) ? 1 : 0;
        #pragma unroll
        for (int e = 0; e < EE; e++) if (e != i1 && lg[e] > lg[i2]) i2 = e;
        float g1 = 1.f / (1.f + __expf(lg[i2] - lg[i1]));
        float g2 = 1.f - g1;
        g_topi[row*2]   = i1; g_topg[row*2]   = g1;
        g_topi[row*2+1] = i2; g_topg[row*2+1] = g2;
        atomicAdd(&g_counts[i1], 1);
        atomicAdd(&g_counts[i2], 1);
    }
}

__global__ void scan_kernel() {
    int s = 0;
    for (int e = 0; e < EE; e++) { g_offsets[e] = s; s += g_counts[e]; }
    g_offsets[EE] = s;
}

__global__ void scatter_kernel() {
    int idx = blockIdx.x * blockDim.x + threadIdx.x;
    if (idx >= NASSIGN) return;
    int e = g_topi[idx];
    int pos = atomicAdd(&g_cursor[e], 1);
    int a = g_offsets[e] + pos;
    g_arow[a]  = idx >> 1;
    g_agate[a] = g_topg[idx];
    g_adst[a]  = idx;
}

__global__ void final_add_kernel(float* __restrict__ out) {
    int idx = blockIdx.x * blockDim.x + threadIdx.x;
    if (idx >= ROWS * DD / 4) return;
    int row = idx >> 8, c4 = (idx & 255) * 4;
    float4 a = *(float4*)&g_h[(size_t)row * DD + c4];
    float4 r0 = *(float4*)&g_r[((size_t)row * 2) * DD + c4];
    float4 r1 = *(float4*)&g_r[((size_t)row * 2 + 1) * DD + c4];
    float4 ov;
    ov.x = a.x + r0.x + r1.x; ov.y = a.y + r0.y + r1.y;
    ov.z = a.z + r0.z + r1.z; ov.w = a.w + r0.w + r1.w;
    *(float4*)&out[(size_t)row * DD + c4] = ov;
}

// ---------------- launch ----------------
extern "C" void kernel_launch(void* const* d_in, const int* in_sizes, int n_in,
                              void* d_out, int out_size) {
    const float* x      = (const float*)d_in[0];
    const float* fcos   = (const float*)d_in[1];
    const float* fsin   = (const float*)d_in[2];
    const float* anw    = (const float*)d_in[3];
    const float* wq     = (const float*)d_in[4];
    const float* wk     = (const float*)d_in[5];
    const float* wv     = (const float*)d_in[6];
    const float* wo     = (const float*)d_in[7];
    const float* fnw    = (const float*)d_in[8];
    const float* rw     = (const float*)d_in[9];
    const float* w1     = (const float*)d_in[10];
    const float* w2     = (const float*)d_in[11];
    float* out = (float*)d_out;

    float *p_hn, *p_q, *p_k, *p_v, *p_o, *p_h, *p_fn;
    cudaGetSymbolAddress((void**)&p_hn, g_hn);
    cudaGetSymbolAddress((void**)&p_q,  g_q);
    cudaGetSymbolAddress((void**)&p_k,  g_k);
    cudaGetSymbolAddress((void**)&p_v,  g_v);
    cudaGetSymbolAddress((void**)&p_o,  g_o);
    cudaGetSymbolAddress((void**)&p_h,  g_h);
    cudaGetSymbolAddress((void**)&p_fn, g_fn);

    static int attrs_set = 0;
    const int ATTN_SMEM = (64*KPAD + 64*KPAD + 128*KPAD) * 4;  // 69632 B
    if (!attrs_set) {
        cudaFuncSetAttribute(attn_tc, cudaFuncAttributeMaxDynamicSharedMemorySize, ATTN_SMEM);
        cudaFuncSetAttribute(tcgemm<0,true>,  cudaFuncAttributeMaxDynamicSharedMemorySize, GEMM_SMEM);
        cudaFuncSetAttribute(tcgemm<0,false>, cudaFuncAttributeMaxDynamicSharedMemorySize, GEMM_SMEM);
        cudaFuncSetAttribute(tcgemm<3,true>,  cudaFuncAttributeMaxDynamicSharedMemorySize, GEMM_SMEM);
        cudaFuncSetAttribute(tcgemm_moe<1>,   cudaFuncAttributeMaxDynamicSharedMemorySize, MOE_SMEM);
        cudaFuncSetAttribute(tcgemm_moe<2>,   cudaFuncAttributeMaxDynamicSharedMemorySize, MOE_SMEM);
        attrs_set = 1;
    }

    zero_kernel<<<1, 32>>>();

    rmsnorm_kernel<<<ROWS, 256>>>(x, anw, p_hn, 1e-5f);

    // QKV projections with fused RoPE
    tcgemm<0,true><<<dim3(8, 32), 256, GEMM_SMEM>>>(p_hn, wq, nullptr, p_q, ROWS, HH*HDD, DD, fcos, fsin);
    tcgemm<3,true><<<dim3(4, 32), 256, GEMM_SMEM>>>(p_hn, wk, wv, nullptr, ROWS, HKK*HDD, DD, fcos, fsin);

    // attention (tensor core)
    attn_tc<<<dim3(SS / 128, HH, BB), 256, ATTN_SMEM>>>(p_q, p_k, p_v);

    // output projection + residual
    tcgemm<0,false><<<dim3(8, 32), 256, GEMM_SMEM>>>(p_o, wo, x, p_h, ROWS, DD, HH*HDD, nullptr, nullptr);

    rmsnorm_kernel<<<ROWS, 256>>>(p_h, fnw, p_fn, 1e-6f);

    // router + compaction
    router_kernel<<<ROWS, 128>>>(p_fn, rw);
    scan_kernel<<<1, 1>>>();
    scatter_kernel<<<NASSIGN / 256, 256>>>();

    // expert GEMMs (256x128 tiles, 64x64 warp tiles)
    tcgemm_moe<1><<<dim3(DHH / BN, NASSIGN / BM2, EE), 256, MOE_SMEM>>>(p_fn, w1, DHH, DD);
    tcgemm_moe<2><<<dim3(DD / BN, NASSIGN / BM2, EE), 256, MOE_SMEM>>>(nullptr, w2, DD, DHH);

    final_add_kernel<<<(ROWS * DD / 4 + 255) / 256, 256>>>(out);

    (void)in_sizes; (void)n_in; (void)out_size;
}